// round 7
// baseline (speedup 1.0000x reference)
#include <cuda_runtime.h>
#include <cuda_bf16.h>
#include <stdint.h>

// out[B=1024, W=201000] f32 one-hot triple scatter over zeros.
// Inputs: z f32 (unused), hID i32[1024], rID i32[1024], tID i32[1024].
//
// Strategy: copy-engine fill (cudaMemsetAsync hits ~98% of HBM write BW,
// beating any SM store kernel's ~88% ceiling) + a latency-minimal scatter
// kernel (one store per thread, 16 CTAs for SM spread).

#define ENTITIES_N  100000
#define RELATIONS_N 1000
#define WIDTH       201000
#define BATCH       1024

__global__ void __launch_bounds__(256) scatter_ones(
    const int* __restrict__ hID,
    const int* __restrict__ rID,
    const int* __restrict__ tID,
    float* __restrict__ out)
{
    const unsigned tid = blockIdx.x * 256u + threadIdx.x;   // [0, 4096)
    const unsigned row = tid >> 2;
    const unsigned j   = tid & 3u;
    if (j == 3u) return;   // 3 stores per row

    // Select index stream without divergent loads: j=0 -> h, 1 -> r, 2 -> t.
    const int* src = (j == 0) ? hID : (j == 1) ? rID : tID;
    const unsigned off = (j == 0) ? 0u
                       : (j == 1) ? (unsigned)ENTITIES_N
                                  : (unsigned)(ENTITIES_N + RELATIONS_N);

    const unsigned col = off + (unsigned)__ldg(&src[row]);
    out[(size_t)row * WIDTH + col] = 1.0f;
}

extern "C" void kernel_launch(void* const* d_in, const int* in_sizes, int n_in,
                              void* d_out, int out_size) {
    const int* hID = (const int*)d_in[1];
    const int* rID = (const int*)d_in[2];
    const int* tID = (const int*)d_in[3];
    float* out = (float*)d_out;

    // Bulk zero on the driver/CE fill path (~7.8 TB/s).
    cudaMemsetAsync(d_out, 0, (size_t)out_size * sizeof(float), 0);

    // 4096 threads, one scattered store each (j==3 lanes idle).
    scatter_ones<<<16, 256>>>(hID, rID, tID, out);
}